// round 1
// baseline (speedup 1.0000x reference)
#include <cuda_runtime.h>
#include <math.h>
#include <float.h>

#define B_TOT   16384
#define NVOX    50000
#define MVIEW   12
#define FDIM    256
#define FAUG    272       // FDIM + 16 (extrinsics)
#define HEADS   8
#define DK      64
#define QDIM    512       // HEADS*DK
#define ODIM    512       // HEADS*DV
#define PE3     24        // PE_ORDER*3

// ---------------- scratch (static device memory; no allocation) ----------------
__device__ unsigned int g_minb[3];
__device__ unsigned int g_maxb[3];
__device__ float g_Q[B_TOT * QDIM];                 // 32 MB
__device__ float g_qW[(size_t)B_TOT * HEADS * FAUG];// 136 MB
__device__ float g_mixed[(size_t)B_TOT * HEADS * FDIM]; // 128 MB

// Ordered-uint encoding so unsigned atomicMin/Max implements float min/max.
__device__ __forceinline__ unsigned int fenc(float f) {
    unsigned int u = __float_as_uint(f);
    return (u & 0x80000000u) ? ~u : (u | 0x80000000u);
}
__device__ __forceinline__ float fdec(unsigned int u) {
    u = (u & 0x80000000u) ? (u & 0x7FFFFFFFu) : ~u;
    return __uint_as_float(u);
}

// ---------------- K0: init min/max ----------------
__global__ void k_init() {
    int t = threadIdx.x;
    if (t < 3) { g_minb[t] = 0xFFFFFFFFu; g_maxb[t] = 0u; }
}

// ---------------- K1: per-component min/max over voxels ----------------
__global__ void k_minmax(const float* __restrict__ vox) {
    float mn[3] = {FLT_MAX, FLT_MAX, FLT_MAX};
    float mx[3] = {-FLT_MAX, -FLT_MAX, -FLT_MAX};
    for (int r = blockIdx.x * blockDim.x + threadIdx.x; r < NVOX;
         r += gridDim.x * blockDim.x) {
        #pragma unroll
        for (int c = 0; c < 3; c++) {
            float v = vox[r * 3 + c];
            mn[c] = fminf(mn[c], v);
            mx[c] = fmaxf(mx[c], v);
        }
    }
    #pragma unroll
    for (int c = 0; c < 3; c++) {
        #pragma unroll
        for (int o = 16; o > 0; o >>= 1) {
            mn[c] = fminf(mn[c], __shfl_xor_sync(0xffffffffu, mn[c], o));
            mx[c] = fmaxf(mx[c], __shfl_xor_sync(0xffffffffu, mx[c], o));
        }
    }
    if ((threadIdx.x & 31) == 0) {
        #pragma unroll
        for (int c = 0; c < 3; c++) {
            atomicMin(&g_minb[c], fenc(mn[c]));
            atomicMax(&g_maxb[c], fenc(mx[c]));
        }
    }
}

// ---------------- K2: query = PE(xyz) @ W_q ----------------
// 256 threads/block, 64 voxels per block (8 per warp). W_q cached in smem (48KB).
__global__ void __launch_bounds__(256) k_query(const int* __restrict__ vidx,
                                               const float* __restrict__ vox,
                                               const float* __restrict__ Wq) {
    __shared__ float sWq[PE3 * QDIM];  // exactly 48 KB
    for (int i = threadIdx.x; i < PE3 * QDIM; i += 256) sWq[i] = Wq[i];
    __syncthreads();

    float mn[3], rng[3];
    #pragma unroll
    for (int c = 0; c < 3; c++) {
        float lo = fdec(g_minb[c]);
        float hi = fdec(g_maxb[c]);
        mn[c] = lo; rng[c] = hi - lo;
    }

    int warp = threadIdx.x >> 5, lane = threadIdx.x & 31;
    int bbase = blockIdx.x * 64 + warp * 8;
    for (int bb = 0; bb < 8; bb++) {
        int b = bbase + bb;
        int idx = vidx[b];
        float xn[3];
        #pragma unroll
        for (int c = 0; c < 3; c++)
            xn[c] = (vox[idx * 3 + c] - mn[c]) / rng[c] - 0.5f;
        float pe[PE3];
        float fr = 1.0f;
        #pragma unroll
        for (int p = 0; p < 8; p++) {
            pe[p * 3 + 0] = sinf(xn[0] * fr);
            pe[p * 3 + 1] = sinf(xn[1] * fr);
            pe[p * 3 + 2] = sinf(xn[2] * fr);
            fr *= 2.0f;
        }
        #pragma unroll 4
        for (int u = 0; u < 16; u++) {
            int col = lane + u * 32;
            float acc = 0.0f;
            #pragma unroll
            for (int j = 0; j < PE3; j++) acc += pe[j] * sWq[j * QDIM + col];
            g_Q[b * QDIM + col] = acc;
        }
    }
}

// ---------------- K3: qW[b,h,f] = sum_d Q[b,h*64+d] * W_k[f, h*64+d] ----------------
// Per head: (16384 x 64) @ (64 x 272)^T. Tiles 64x64, K=64 single slab.
__global__ void __launch_bounds__(256) k_qw(const float* __restrict__ Wk) {
    __shared__ float As[64][68];  // As[k][b-row]
    __shared__ float Bs[64][68];  // Bs[k][f-col]
    int h = blockIdx.z;
    int b0 = blockIdx.y * 64;
    int f0 = blockIdx.x * 64;
    int tid = threadIdx.x;

    for (int i = tid; i < 64 * 16; i += 256) {
        int row = i >> 4, k4 = (i & 15) * 4;
        float4 v = *(const float4*)&g_Q[(size_t)(b0 + row) * QDIM + h * 64 + k4];
        As[k4 + 0][row] = v.x; As[k4 + 1][row] = v.y;
        As[k4 + 2][row] = v.z; As[k4 + 3][row] = v.w;
    }
    for (int i = tid; i < 64 * 16; i += 256) {
        int ff = i >> 4, k4 = (i & 15) * 4;
        float4 v = make_float4(0.f, 0.f, 0.f, 0.f);
        if (f0 + ff < FAUG)
            v = *(const float4*)&Wk[(size_t)(f0 + ff) * QDIM + h * 64 + k4];
        Bs[k4 + 0][ff] = v.x; Bs[k4 + 1][ff] = v.y;
        Bs[k4 + 2][ff] = v.z; Bs[k4 + 3][ff] = v.w;
    }
    __syncthreads();

    int ty = tid >> 4, tx = tid & 15;
    float acc[4][4] = {};
    #pragma unroll 16
    for (int k = 0; k < 64; k++) {
        float a[4], bv[4];
        #pragma unroll
        for (int i = 0; i < 4; i++) a[i] = As[k][ty * 4 + i];
        #pragma unroll
        for (int j = 0; j < 4; j++) bv[j] = Bs[k][tx * 4 + j];
        #pragma unroll
        for (int i = 0; i < 4; i++)
            #pragma unroll
            for (int j = 0; j < 4; j++) acc[i][j] += a[i] * bv[j];
    }
    #pragma unroll
    for (int i = 0; i < 4; i++) {
        int b = b0 + ty * 4 + i;
        #pragma unroll
        for (int j = 0; j < 4; j++) {
            int f = f0 + tx * 4 + j;
            if (f < FAUG)
                g_qW[(size_t)b * (HEADS * FAUG) + h * FAUG + f] = acc[i][j];
        }
    }
}

// ---------------- K4: gather + logits + softmax + feature mix ----------------
// One CTA per query voxel; 256 threads.
__global__ void __launch_bounds__(256) k_attn(const int* __restrict__ vidx,
                                              const float* __restrict__ feats_g,
                                              const float* __restrict__ scores_g,
                                              const int* __restrict__ camids,
                                              const float* __restrict__ extr) {
    __shared__ float sf[MVIEW][FDIM];       // 12 KB gathered features
    __shared__ float sqw[HEADS * FAUG];     // 8.7 KB
    __shared__ float sext[MVIEW][16];
    __shared__ float sp[HEADS][MVIEW];
    __shared__ float smask[MVIEW];
    __shared__ int   scam[MVIEW];

    int b = blockIdx.x;
    int tid = threadIdx.x;
    int idx = vidx[b];

    const float4* fsrc = (const float4*)(feats_g + (size_t)idx * MVIEW * FDIM);
    float4* fdst = (float4*)&sf[0][0];
    for (int i = tid; i < MVIEW * FDIM / 4; i += 256) fdst[i] = fsrc[i];

    const float4* qsrc = (const float4*)(g_qW + (size_t)b * HEADS * FAUG);
    float4* qdst = (float4*)sqw;
    for (int i = tid; i < HEADS * FAUG / 4; i += 256) qdst[i] = qsrc[i];

    if (tid < MVIEW) {
        float s = scores_g[(size_t)idx * MVIEW + tid];
        smask[tid] = (s < 0.0f) ? -1e30f : 0.0f;
        scam[tid] = camids[(size_t)idx * MVIEW + tid];
    }
    __syncthreads();
    if (tid < MVIEW * 16) {
        int m = tid >> 4, j = tid & 15;
        sext[m][j] = extr[scam[m] * 16 + j];
    }
    __syncthreads();

    // head w handled by warp w
    int w = tid >> 5, lane = tid & 31;
    float lg[MVIEW];
    #pragma unroll
    for (int m = 0; m < MVIEW; m++) {
        float s = 0.0f;
        #pragma unroll
        for (int u = 0; u < 8; u++) {
            int t = lane + u * 32;
            s += sf[m][t] * sqw[w * FAUG + t];
        }
        if (lane < 16) s += sext[m][lane] * sqw[w * FAUG + 256 + lane];
        #pragma unroll
        for (int o = 16; o > 0; o >>= 1) s += __shfl_xor_sync(0xffffffffu, s, o);
        lg[m] = s * 0.125f + smask[m];   // valid on lane 0
    }
    if (lane == 0) {
        float mx = -FLT_MAX;
        #pragma unroll
        for (int m = 0; m < MVIEW; m++) mx = fmaxf(mx, lg[m]);
        float e[MVIEW], sum = 0.0f;
        #pragma unroll
        for (int m = 0; m < MVIEW; m++) { e[m] = expf(lg[m] - mx); sum += e[m]; }
        float inv = 1.0f / sum;
        #pragma unroll
        for (int m = 0; m < MVIEW; m++) sp[w][m] = e[m] * inv;
    }
    __syncthreads();

    // mixed[b,h,t] = sum_m p[h,m] * feats[m,t]
    float fv[MVIEW];
    #pragma unroll
    for (int m = 0; m < MVIEW; m++) fv[m] = sf[m][tid];
    #pragma unroll
    for (int h = 0; h < HEADS; h++) {
        float acc = 0.0f;
        #pragma unroll
        for (int m = 0; m < MVIEW; m++) acc += sp[h][m] * fv[m];
        g_mixed[(size_t)b * (HEADS * FDIM) + h * FDIM + tid] = acc;
    }
}

// ---------------- K5: out[b,h*64+j] = sum_f mixed[b,h,f] * W_v[f,h*64+j] ----------------
// Per head: (16384 x 256) @ (256 x 64). Tiles 64x64, K in 4 slabs of 64.
__global__ void __launch_bounds__(256) k_out(const float* __restrict__ Wv,
                                             float* __restrict__ out) {
    __shared__ float As[64][68];  // As[k][b-row]
    __shared__ float Bs[64][68];  // Bs[k][j-col]
    int h = blockIdx.z;
    int b0 = blockIdx.y * 64;
    int tid = threadIdx.x;
    int ty = tid >> 4, tx = tid & 15;
    float acc[4][4] = {};

    for (int k0 = 0; k0 < FDIM; k0 += 64) {
        for (int i = tid; i < 64 * 16; i += 256) {
            int row = i >> 4, k4 = (i & 15) * 4;
            float4 v = *(const float4*)&g_mixed[(size_t)(b0 + row) * (HEADS * FDIM)
                                                + h * FDIM + k0 + k4];
            As[k4 + 0][row] = v.x; As[k4 + 1][row] = v.y;
            As[k4 + 2][row] = v.z; As[k4 + 3][row] = v.w;
        }
        for (int i = tid; i < 64 * 16; i += 256) {
            int kk = i >> 4, j4 = (i & 15) * 4;
            float4 v = *(const float4*)&Wv[(size_t)(k0 + kk) * ODIM + h * 64 + j4];
            *(float4*)&Bs[kk][j4] = v;
        }
        __syncthreads();
        #pragma unroll 16
        for (int k = 0; k < 64; k++) {
            float a[4], bv[4];
            #pragma unroll
            for (int i = 0; i < 4; i++) a[i] = As[k][ty * 4 + i];
            #pragma unroll
            for (int j = 0; j < 4; j++) bv[j] = Bs[k][tx * 4 + j];
            #pragma unroll
            for (int i = 0; i < 4; i++)
                #pragma unroll
                for (int j = 0; j < 4; j++) acc[i][j] += a[i] * bv[j];
        }
        __syncthreads();
    }
    #pragma unroll
    for (int i = 0; i < 4; i++) {
        int b = b0 + ty * 4 + i;
        #pragma unroll
        for (int j = 0; j < 4; j++)
            out[(size_t)b * ODIM + h * 64 + tx * 4 + j] = acc[i][j];
    }
}

// ---------------- launcher ----------------
extern "C" void kernel_launch(void* const* d_in, const int* in_sizes, int n_in,
                              void* d_out, int out_size) {
    const int*   vidx = (const int*)d_in[0];    // vox_indices (B,)
    const float* vox  = (const float*)d_in[1];  // voxels (N_VOX,3)
    const float* vf   = (const float*)d_in[2];  // voxel_features (N_VOX,12,256)
    const float* vs   = (const float*)d_in[3];  // voxel_feature_scores (N_VOX,12)
    const int*   cam  = (const int*)d_in[4];    // camera_ids (N_VOX,12)
    const float* ext  = (const float*)d_in[5];  // extrinsics (48,16)
    const float* Wq   = (const float*)d_in[6];  // (24,512)
    const float* Wk   = (const float*)d_in[7];  // (272,512)
    const float* Wv   = (const float*)d_in[8];  // (256,512)
    float* out = (float*)d_out;

    k_init<<<1, 32>>>();
    k_minmax<<<64, 256>>>(vox);
    k_query<<<B_TOT / 64, 256>>>(vidx, vox, Wq);
    k_qw<<<dim3(5, B_TOT / 64, 8), 256>>>(Wk);
    k_attn<<<B_TOT, 256>>>(vidx, vf, vs, cam, ext);
    k_out<<<dim3(1, B_TOT / 64, 8), 256>>>(Wv, out);
}

// round 2
// speedup vs baseline: 1.2286x; 1.2286x over previous
#include <cuda_runtime.h>
#include <math.h>
#include <float.h>

#define B_TOT   16384
#define NVOX    50000
#define MVIEW   12
#define FDIM    256
#define FAUG    272       // FDIM + 16 (extrinsics)
#define HEADS   8
#define QDIM    512       // HEADS*DK
#define ODIM    512       // HEADS*DV
#define PE3     24        // PE_ORDER*3
#define CDIM    2176      // HEADS*FAUG

// ---------------- scratch (static device memory; no allocation) ----------------
__device__ unsigned int g_minb[3];
__device__ unsigned int g_maxb[3];
__device__ float g_pe[B_TOT * PE3];                      // 1.5 MB
__device__ float g_C2[PE3 * CDIM];                       // 209 KB
__device__ float g_qW[(size_t)B_TOT * CDIM];             // 142 MB
__device__ float g_mixed[(size_t)B_TOT * HEADS * FDIM];  // 128 MB

// Ordered-uint encoding so unsigned atomicMin/Max implements float min/max.
__device__ __forceinline__ unsigned int fenc(float f) {
    unsigned int u = __float_as_uint(f);
    return (u & 0x80000000u) ? ~u : (u | 0x80000000u);
}
__device__ __forceinline__ float fdec(unsigned int u) {
    u = (u & 0x80000000u) ? (u & 0x7FFFFFFFu) : ~u;
    return __uint_as_float(u);
}

// ---------------- K0: init min/max ----------------
__global__ void k_init() {
    int t = threadIdx.x;
    if (t < 3) { g_minb[t] = 0xFFFFFFFFu; g_maxb[t] = 0u; }
}

// ---------------- K1: per-component min/max over voxels ----------------
__global__ void k_minmax(const float* __restrict__ vox) {
    float mn[3] = {FLT_MAX, FLT_MAX, FLT_MAX};
    float mx[3] = {-FLT_MAX, -FLT_MAX, -FLT_MAX};
    for (int r = blockIdx.x * blockDim.x + threadIdx.x; r < NVOX;
         r += gridDim.x * blockDim.x) {
        #pragma unroll
        for (int c = 0; c < 3; c++) {
            float v = vox[r * 3 + c];
            mn[c] = fminf(mn[c], v);
            mx[c] = fmaxf(mx[c], v);
        }
    }
    #pragma unroll
    for (int c = 0; c < 3; c++) {
        #pragma unroll
        for (int o = 16; o > 0; o >>= 1) {
            mn[c] = fminf(mn[c], __shfl_xor_sync(0xffffffffu, mn[c], o));
            mx[c] = fmaxf(mx[c], __shfl_xor_sync(0xffffffffu, mx[c], o));
        }
    }
    if ((threadIdx.x & 31) == 0) {
        #pragma unroll
        for (int c = 0; c < 3; c++) {
            atomicMin(&g_minb[c], fenc(mn[c]));
            atomicMax(&g_maxb[c], fenc(mx[c]));
        }
    }
}

// ---------------- K2: pe[b, 24] = sinusoidal PE of normalized xyz ----------------
__global__ void __launch_bounds__(256) k_pe(const int* __restrict__ vidx,
                                            const float* __restrict__ vox) {
    int b = blockIdx.x * 256 + threadIdx.x;
    if (b >= B_TOT) return;
    float mn[3], rng[3];
    #pragma unroll
    for (int c = 0; c < 3; c++) {
        float lo = fdec(g_minb[c]);
        float hi = fdec(g_maxb[c]);
        mn[c] = lo; rng[c] = hi - lo;
    }
    int idx = vidx[b];
    float xn[3];
    #pragma unroll
    for (int c = 0; c < 3; c++)
        xn[c] = (vox[idx * 3 + c] - mn[c]) / rng[c] - 0.5f;
    float fr = 1.0f;
    float* dst = g_pe + (size_t)b * PE3;
    #pragma unroll
    for (int p = 0; p < 8; p++) {
        dst[p * 3 + 0] = sinf(xn[0] * fr);
        dst[p * 3 + 1] = sinf(xn[1] * fr);
        dst[p * 3 + 2] = sinf(xn[2] * fr);
        fr *= 2.0f;
    }
}

// ---------------- K3: C2[j, h*272+f] = sum_d Wq[j, h*64+d] * Wk[f, h*64+d] ----------
__global__ void __launch_bounds__(256) k_C2(const float* __restrict__ Wq,
                                            const float* __restrict__ Wk) {
    int i = blockIdx.x * 256 + threadIdx.x;
    if (i >= PE3 * CDIM) return;
    int j = i / CDIM;
    int col = i - j * CDIM;
    int h = col / FAUG;
    int f = col - h * FAUG;
    const float* wq = Wq + j * QDIM + h * 64;
    const float* wk = Wk + (size_t)f * QDIM + h * 64;
    float acc = 0.0f;
    #pragma unroll 16
    for (int d = 0; d < 64; d++) acc += wq[d] * wk[d];
    g_C2[i] = acc;
}

// ---------------- K4: qW = pe @ C2  (M=16384, N=2176, K=24) ----------------
// Tiles 128x128, 256 threads, 8x8 register blocking. Write-bandwidth bound.
__global__ void __launch_bounds__(256) k_qw2() {
    __shared__ float peS[PE3][132];   // [k][row], padded
    __shared__ float c2S[PE3][132];   // [k][col], padded
    int b0 = blockIdx.y * 128;
    int c0 = blockIdx.x * 128;
    int tid = threadIdx.x;

    // load pe rows (contiguous 3072 floats), transposed into smem
    for (int i = tid; i < 128 * PE3; i += 256) {
        int row = i / PE3;
        int j = i - row * PE3;
        peS[j][row] = g_pe[(size_t)b0 * PE3 + i];
    }
    // load C2 tile (no transpose)
    for (int i = tid; i < PE3 * 128; i += 256) {
        int j = i >> 7, c = i & 127;
        c2S[j][c] = g_C2[j * CDIM + c0 + c];
    }
    __syncthreads();

    int ty = tid >> 4, tx = tid & 15;
    float acc[8][8] = {};
    #pragma unroll
    for (int k = 0; k < PE3; k++) {
        float a[8], bv[8];
        *(float4*)&a[0] = *(float4*)&peS[k][ty * 8];
        *(float4*)&a[4] = *(float4*)&peS[k][ty * 8 + 4];
        *(float4*)&bv[0] = *(float4*)&c2S[k][tx * 8];
        *(float4*)&bv[4] = *(float4*)&c2S[k][tx * 8 + 4];
        #pragma unroll
        for (int i = 0; i < 8; i++)
            #pragma unroll
            for (int j = 0; j < 8; j++) acc[i][j] += a[i] * bv[j];
    }
    #pragma unroll
    for (int i = 0; i < 8; i++) {
        size_t base = (size_t)(b0 + ty * 8 + i) * CDIM + c0 + tx * 8;
        *(float4*)&g_qW[base]     = make_float4(acc[i][0], acc[i][1], acc[i][2], acc[i][3]);
        *(float4*)&g_qW[base + 4] = make_float4(acc[i][4], acc[i][5], acc[i][6], acc[i][7]);
    }
}

// ---------------- K5: gather + logits + softmax + feature mix ----------------
__global__ void __launch_bounds__(256) k_attn(const int* __restrict__ vidx,
                                              const float* __restrict__ feats_g,
                                              const float* __restrict__ scores_g,
                                              const int* __restrict__ camids,
                                              const float* __restrict__ extr) {
    __shared__ float sf[MVIEW][FDIM];       // 12 KB gathered features
    __shared__ float sqw[CDIM];             // 8.7 KB
    __shared__ float sext[MVIEW][16];
    __shared__ float sp[HEADS][MVIEW];
    __shared__ float smask[MVIEW];
    __shared__ int   scam[MVIEW];

    int b = blockIdx.x;
    int tid = threadIdx.x;
    int idx = vidx[b];

    const float4* fsrc = (const float4*)(feats_g + (size_t)idx * MVIEW * FDIM);
    float4* fdst = (float4*)&sf[0][0];
    for (int i = tid; i < MVIEW * FDIM / 4; i += 256) fdst[i] = fsrc[i];

    const float4* qsrc = (const float4*)(g_qW + (size_t)b * CDIM);
    float4* qdst = (float4*)sqw;
    for (int i = tid; i < CDIM / 4; i += 256) qdst[i] = qsrc[i];

    if (tid < MVIEW) {
        float s = scores_g[(size_t)idx * MVIEW + tid];
        smask[tid] = (s < 0.0f) ? -1e30f : 0.0f;
        scam[tid] = camids[(size_t)idx * MVIEW + tid];
    }
    __syncthreads();
    if (tid < MVIEW * 16) {
        int m = tid >> 4, j = tid & 15;
        sext[m][j] = extr[scam[m] * 16 + j];
    }
    __syncthreads();

    // head w handled by warp w
    int w = tid >> 5, lane = tid & 31;
    float lg[MVIEW];
    #pragma unroll
    for (int m = 0; m < MVIEW; m++) {
        float s = 0.0f;
        #pragma unroll
        for (int u = 0; u < 8; u++) {
            int t = lane + u * 32;
            s += sf[m][t] * sqw[w * FAUG + t];
        }
        if (lane < 16) s += sext[m][lane] * sqw[w * FAUG + 256 + lane];
        #pragma unroll
        for (int o = 16; o > 0; o >>= 1) s += __shfl_xor_sync(0xffffffffu, s, o);
        lg[m] = s * 0.125f + smask[m];   // valid on lane 0
    }
    if (lane == 0) {
        float mx = -FLT_MAX;
        #pragma unroll
        for (int m = 0; m < MVIEW; m++) mx = fmaxf(mx, lg[m]);
        float e[MVIEW], sum = 0.0f;
        #pragma unroll
        for (int m = 0; m < MVIEW; m++) { e[m] = expf(lg[m] - mx); sum += e[m]; }
        float inv = 1.0f / sum;
        #pragma unroll
        for (int m = 0; m < MVIEW; m++) sp[w][m] = e[m] * inv;
    }
    __syncthreads();

    // mixed[b,h,t] = sum_m p[h,m] * feats[m,t]
    float fv[MVIEW];
    #pragma unroll
    for (int m = 0; m < MVIEW; m++) fv[m] = sf[m][tid];
    #pragma unroll
    for (int h = 0; h < HEADS; h++) {
        float acc = 0.0f;
        #pragma unroll
        for (int m = 0; m < MVIEW; m++) acc += sp[h][m] * fv[m];
        g_mixed[(size_t)b * (HEADS * FDIM) + h * FDIM + tid] = acc;
    }
}

// ---------------- K6: out[b, h*64+j] = mixed[b,h,:] @ Wv_h ----------------
// One CTA per (head, 128-row chunk). Full 64 KB W_v head-slice resident in smem.
#define OUT_SMEM ((256 * 64 + 32 * 132) * 4)
__global__ void __launch_bounds__(256) k_out(const float* __restrict__ Wv,
                                             float* __restrict__ out) {
    extern __shared__ float sm[];
    float* WvS = sm;                 // [256][64]
    float* As  = sm + 256 * 64;      // [32][132] (k-major, padded)
    int h = blockIdx.y;
    int b0 = blockIdx.x * 128;
    int tid = threadIdx.x;

    // load W_v head slice once (coalesced float4)
    for (int i = tid; i < 256 * 16; i += 256) {
        int k = i >> 4, c4 = (i & 15) * 4;
        *(float4*)&WvS[k * 64 + c4] = *(const float4*)&Wv[(size_t)k * ODIM + h * 64 + c4];
    }

    int ty = tid >> 4, tx = tid & 15;
    float acc[8][4] = {};

    for (int k0 = 0; k0 < FDIM; k0 += 32) {
        __syncthreads();
        // load A slab transposed: As[k][row]
        for (int i = tid; i < 128 * 8; i += 256) {
            int row = i >> 3, k4 = (i & 7) * 4;
            float4 v = *(const float4*)&g_mixed[(size_t)(b0 + row) * (HEADS * FDIM)
                                                + h * FDIM + k0 + k4];
            As[(k4 + 0) * 132 + row] = v.x;
            As[(k4 + 1) * 132 + row] = v.y;
            As[(k4 + 2) * 132 + row] = v.z;
            As[(k4 + 3) * 132 + row] = v.w;
        }
        __syncthreads();
        #pragma unroll
        for (int kk = 0; kk < 32; kk++) {
            float a[8], bv[4];
            *(float4*)&a[0] = *(float4*)&As[kk * 132 + ty * 8];
            *(float4*)&a[4] = *(float4*)&As[kk * 132 + ty * 8 + 4];
            *(float4*)&bv[0] = *(float4*)&WvS[(k0 + kk) * 64 + tx * 4];
            #pragma unroll
            for (int i = 0; i < 8; i++)
                #pragma unroll
                for (int j = 0; j < 4; j++) acc[i][j] += a[i] * bv[j];
        }
    }
    #pragma unroll
    for (int i = 0; i < 8; i++) {
        size_t row = b0 + ty * 8 + i;
        *(float4*)&out[row * ODIM + h * 64 + tx * 4] =
            make_float4(acc[i][0], acc[i][1], acc[i][2], acc[i][3]);
    }
}

// ---------------- launcher ----------------
extern "C" void kernel_launch(void* const* d_in, const int* in_sizes, int n_in,
                              void* d_out, int out_size) {
    const int*   vidx = (const int*)d_in[0];    // vox_indices (B,)
    const float* vox  = (const float*)d_in[1];  // voxels (N_VOX,3)
    const float* vf   = (const float*)d_in[2];  // voxel_features (N_VOX,12,256)
    const float* vs   = (const float*)d_in[3];  // voxel_feature_scores (N_VOX,12)
    const int*   cam  = (const int*)d_in[4];    // camera_ids (N_VOX,12)
    const float* ext  = (const float*)d_in[5];  // extrinsics (48,16)
    const float* Wq   = (const float*)d_in[6];  // (24,512)
    const float* Wk   = (const float*)d_in[7];  // (272,512)
    const float* Wv   = (const float*)d_in[8];  // (256,512)
    float* out = (float*)d_out;

    cudaFuncSetAttribute(k_out, cudaFuncAttributeMaxDynamicSharedMemorySize, OUT_SMEM);

    k_init<<<1, 32>>>();
    k_minmax<<<64, 256>>>(vox);
    k_pe<<<B_TOT / 256, 256>>>(vidx, vox);
    k_C2<<<(PE3 * CDIM + 255) / 256, 256>>>(Wq, Wk);
    k_qw2<<<dim3(CDIM / 128, B_TOT / 128), 256>>>();
    k_attn<<<B_TOT, 256>>>(vidx, vf, vs, cam, ext);
    k_out<<<dim3(B_TOT / 128, HEADS), 256, OUT_SMEM>>>(Wv, out);
}